// round 2
// baseline (speedup 1.0000x reference)
#include <cuda_runtime.h>

#define Bb  2
#define Pp  128
#define Cc  8
#define Hh  16
#define KVHh 4
#define Gg  4
#define Dd  64
#define Ee  1024
#define EKVv 256
#define Tt  1024

// ---------------- scratch (device globals; no allocation allowed) -----------
__device__ float g_q[Bb*Tt*Ee];          // [B,T,E]  q = hs @ Wq
__device__ float g_kv[Bb*Tt*2*EKVv];     // [B,T,512] gk | v
__device__ float g_tk[Pp*EKVv];          // pos_emb @ Wpos
__device__ float g_ck[Cc*EKVv];          // chan_emb @ Wchan
__device__ float g_time[Bb*Hh*Tt*Pp];    // time_att (pre-shift)
__device__ float g_chan[Bb*Hh*Tt*Cc];    // chan_att (pre-shift)
__device__ float g_ao[Bb*Tt*Ee];         // attention output (pre out-proj)

// ---------------- simple fp32 SGEMM: C = A(MxK) @ B(KxN), row-major ---------
__global__ void sgemm(const float* __restrict__ A, const float* __restrict__ B,
                      float* __restrict__ Cmat, int M, int N, int K) {
    __shared__ float As[16][64];
    __shared__ float Bs[16][64];
    int tid = threadIdx.x;
    int m0 = blockIdx.y * 64, n0 = blockIdx.x * 64;
    int ty = tid >> 4, tx = tid & 15;
    int arow = tid >> 2;          // 0..63
    int acol = (tid & 3) * 4;     // 0..12
    int brow = tid >> 4;          // 0..15
    int bcol = (tid & 15) * 4;    // 0..60
    float acc[4][4];
#pragma unroll
    for (int i = 0; i < 4; i++)
#pragma unroll
        for (int j = 0; j < 4; j++) acc[i][j] = 0.f;

    for (int k0 = 0; k0 < K; k0 += 16) {
        int mm = m0 + arow;
#pragma unroll
        for (int j = 0; j < 4; j++) {
            int kk = k0 + acol + j;
            As[acol + j][arow] = (mm < M && kk < K) ? A[(size_t)mm * K + kk] : 0.f;
        }
        int kk = k0 + brow;
#pragma unroll
        for (int j = 0; j < 4; j++) {
            int nn = n0 + bcol + j;
            Bs[brow][bcol + j] = (kk < K && nn < N) ? B[(size_t)kk * N + nn] : 0.f;
        }
        __syncthreads();
#pragma unroll
        for (int k = 0; k < 16; k++) {
            float ra[4], rb[4];
#pragma unroll
            for (int i = 0; i < 4; i++) ra[i] = As[k][ty * 4 + i];
#pragma unroll
            for (int i = 0; i < 4; i++) rb[i] = Bs[k][tx * 4 + i];
#pragma unroll
            for (int i = 0; i < 4; i++)
#pragma unroll
                for (int j = 0; j < 4; j++) acc[i][j] += ra[i] * rb[j];
        }
        __syncthreads();
    }
#pragma unroll
    for (int i = 0; i < 4; i++) {
        int mm = m0 + ty * 4 + i;
        if (mm >= M) continue;
#pragma unroll
        for (int j = 0; j < 4; j++) {
            int nn = n0 + tx * 4 + j;
            if (nn < N) Cmat[(size_t)mm * N + nn] = acc[i][j];
        }
    }
}

// ---------------- time_att[b,h,t,p] = (q[t]+tb_h) . tk_h[p] ------------------
__global__ void time_att_kernel(const float* __restrict__ q,
                                const float* __restrict__ bias) {
    __shared__ float qs[32][65];
    __shared__ float tks[128][64];
    int bh = blockIdx.x;
    int b = bh / Hh, h = bh % Hh, kvh = h / Gg;
    int t0 = blockIdx.y * 32;
    int tid = threadIdx.x;
    for (int i = tid; i < 32 * 64; i += 256) {
        int r = i >> 6, d = i & 63;
        qs[r][d] = q[((size_t)(b * Tt + t0 + r)) * Ee + h * Dd + d]
                 + bias[EKVv + kvh * Dd + d];
    }
    for (int i = tid; i < 128 * 64; i += 256) {
        int p = i >> 6, d = i & 63;
        tks[p][d] = g_tk[p * EKVv + kvh * Dd + d];
    }
    __syncthreads();
    int r = tid & 31;
    int pb = (tid >> 5) * 16;
    float acc[16];
#pragma unroll
    for (int j = 0; j < 16; j++) acc[j] = 0.f;
    for (int d = 0; d < 64; d++) {
        float qv = qs[r][d];
#pragma unroll
        for (int j = 0; j < 16; j++) acc[j] += qv * tks[pb + j][d];
    }
    float* dst = g_time + ((size_t)bh * Tt + t0 + r) * Pp + pb;
#pragma unroll
    for (int j = 0; j < 16; j++) dst[j] = acc[j];
}

// ---------------- chan_att[b,h,t,c] = (q[t]+cb_h) . ck_h[c] ------------------
__global__ void chan_att_kernel(const float* __restrict__ q,
                                const float* __restrict__ bias) {
    __shared__ float qs[32][65];
    __shared__ float cks[8][65];
    int bh = blockIdx.x;
    int b = bh / Hh, h = bh % Hh, kvh = h / Gg;
    int t0 = blockIdx.y * 32;
    int tid = threadIdx.x;
    for (int i = tid; i < 32 * 64; i += 256) {
        int r = i >> 6, d = i & 63;
        qs[r][d] = q[((size_t)(b * Tt + t0 + r)) * Ee + h * Dd + d]
                 + bias[2 * EKVv + kvh * Dd + d];
    }
    // FIX (R1 bug): 8*64 = 512 elements but only 256 threads — loop, don't guard.
    for (int i = tid; i < 8 * 64; i += 256) {
        int c = i >> 6, d = i & 63;
        cks[c][d] = g_ck[c * EKVv + kvh * Dd + d];
    }
    __syncthreads();
    int r = tid >> 3, c = tid & 7;
    float acc = 0.f;
#pragma unroll
    for (int d = 0; d < 64; d++) acc += qs[r][d] * cks[c][d];
    g_chan[((size_t)bh * Tt + t0 + r) * Cc + c] = acc;
}

// ---------------- attention core: one block per (b, h, pt) -------------------
__global__ void attn_kernel(const float* __restrict__ q,
                            const float* __restrict__ bias) {
    __shared__ float qg[8][65];      // q + global bias
    __shared__ float lg[8][1025];    // logits -> exp weights
    __shared__ float rinv[8];
    int blk = blockIdx.x;
    int pt = blk % Pp;
    int h  = (blk / Pp) % Hh;
    int b  = blk / (Pp * Hh);
    int kvh = h / Gg;
    int tid = threadIdx.x;
    int t0 = pt * Cc;

    for (int i = tid; i < 8 * 64; i += 256) {
        int c = i >> 6, d = i & 63;
        qg[c][d] = q[((size_t)(b * Tt + t0 + c)) * Ee + h * Dd + d]
                 + bias[kvh * Dd + d];
    }
    __syncthreads();

    int S = (pt + 1) * Cc;                       // causal extent (patch-level)
    const float* tbase = g_time + (size_t)(b * Hh + h) * Tt * Pp;
    const float* cbase = g_chan + (size_t)(b * Hh + h) * Tt * Cc;

    // base logits: rel-shifted time + rel-shifted chan
    for (int idx = tid; idx < S * 8; idx += 256) {
        int s = idx >> 3, c = idx & 7;
        int t = t0 + c;
        int ps = s >> 3, cs = s & 7;
        int m = (t + 1) * Pp + ps;
        int i2 = m / (Tt + 1);
        float tv = 0.f;
        if (m - i2 * (Tt + 1) != 0) tv = tbase[m - i2 - 1];  // flat-index gather
        int dc = c - cs; dc = dc < 0 ? -dc : dc;
        float cv = cbase[t * Cc + (Cc - 1 - dc)];
        lg[c][s] = tv + cv;
    }
    __syncthreads();

    // global term only inside the wm band (last patch row: everywhere)
    int gLow = (pt == Pp - 1) ? 0 : ((pt > 10 ? pt - 10 : 0) * Cc);
    int nG = (S - gLow) * 8;
    for (int idx = tid; idx < nG; idx += 256) {
        int s = gLow + (idx >> 3);
        int c = idx & 7;
        const float4* gk4 = (const float4*)(g_kv
            + ((size_t)(b * Tt + s)) * (2 * EKVv) + kvh * Dd);
        float acc = 0.f;
#pragma unroll
        for (int d4 = 0; d4 < 16; d4++) {
            float4 gv = gk4[d4];
            acc += qg[c][d4 * 4 + 0] * gv.x + qg[c][d4 * 4 + 1] * gv.y
                 + qg[c][d4 * 4 + 2] * gv.z + qg[c][d4 * 4 + 3] * gv.w;
        }
        lg[c][s] += acc;
    }
    __syncthreads();

    // softmax: warp w owns row w (scale 1/sqrt(D)=0.125 applied here)
    int w = tid >> 5, lane = tid & 31;
    {
        float mx = -1e30f;
        for (int s = lane; s < S; s += 32) mx = fmaxf(mx, lg[w][s] * 0.125f);
#pragma unroll
        for (int o = 16; o > 0; o >>= 1)
            mx = fmaxf(mx, __shfl_xor_sync(0xffffffffu, mx, o));
        float sum = 0.f;
        for (int s = lane; s < S; s += 32) {
            float e = __expf(lg[w][s] * 0.125f - mx);
            lg[w][s] = e;
            sum += e;
        }
#pragma unroll
        for (int o = 16; o > 0; o >>= 1)
            sum += __shfl_xor_sync(0xffffffffu, sum, o);
        if (lane == 0) rinv[w] = 1.f / sum;
    }
    __syncthreads();

    // out[c,d] = sum_s w[c,s] * v[s,d]
    for (int idx = tid; idx < 8 * 64; idx += 256) {
        int c = idx >> 6, d = idx & 63;
        const float* vcol = g_kv + (size_t)b * Tt * (2 * EKVv) + EKVv + kvh * Dd + d;
        float acc = 0.f;
#pragma unroll 4
        for (int s = 0; s < S; s++) acc += lg[c][s] * vcol[(size_t)s * (2 * EKVv)];
        g_ao[((size_t)(b * Tt + t0 + c)) * Ee + h * Dd + d] = acc * rinv[c];
    }
}

// ---------------- launch ----------------------------------------------------
extern "C" void kernel_launch(void* const* d_in, const int* in_sizes, int n_in,
                              void* d_out, int out_size) {
    const float* hs    = (const float*)d_in[0];
    const float* pe    = (const float*)d_in[1];
    const float* ce    = (const float*)d_in[2];
    const float* Wq    = (const float*)d_in[3];
    const float* Wkv   = (const float*)d_in[4];
    const float* Wpos  = (const float*)d_in[5];
    const float* Wchan = (const float*)d_in[6];
    const float* Wproj = (const float*)d_in[7];
    const float* bias  = (const float*)d_in[8];

    float *q, *kv, *tk, *ck, *ao;
    cudaGetSymbolAddress((void**)&q,  g_q);
    cudaGetSymbolAddress((void**)&kv, g_kv);
    cudaGetSymbolAddress((void**)&tk, g_tk);
    cudaGetSymbolAddress((void**)&ck, g_ck);
    cudaGetSymbolAddress((void**)&ao, g_ao);

    // projections
    sgemm<<<dim3(Ee / 64, (Bb * Tt) / 64), 256>>>(hs, Wq, q, Bb * Tt, Ee, Ee);
    sgemm<<<dim3((2 * EKVv) / 64, (Bb * Tt) / 64), 256>>>(hs, Wkv, kv, Bb * Tt, 2 * EKVv, Ee);
    sgemm<<<dim3(EKVv / 64, Pp / 64), 256>>>(pe, Wpos, tk, Pp, EKVv, Ee);
    sgemm<<<dim3(EKVv / 64, 1), 256>>>(ce, Wchan, ck, Cc, EKVv, Ee);

    // relative logits
    time_att_kernel<<<dim3(Bb * Hh, Tt / 32), 256>>>(q, bias);
    chan_att_kernel<<<dim3(Bb * Hh, Tt / 32), 256>>>(q, bias);

    // attention core
    attn_kernel<<<Bb * Hh * Pp, 256>>>(q, bias);

    // output projection -> d_out
    sgemm<<<dim3(Ee / 64, (Bb * Tt) / 64), 256>>>(ao, Wproj, (float*)d_out, Bb * Tt, Ee, Ee);
}